// round 5
// baseline (speedup 1.0000x reference)
#include <cuda_runtime.h>
#include <cstdint>

#define Bq   4
#define Sq   2048
#define Dq   1024
#define Hq   16
#define HDq  64
#define Mq   (Bq*Sq)

__device__ float g_xn[(size_t)Mq*Dq];   // normalized input
__device__ float g_q[(size_t)Mq*Dq];
__device__ float g_k[(size_t)Mq*Dq];
__device__ float g_v[(size_t)Mq*Dq];
__device__ float g_ctx[(size_t)Mq*Dq];

// ---------------------------------------------------------------------------
// helpers
// ---------------------------------------------------------------------------
__device__ __forceinline__ uint32_t f2tf(float f) {
    uint32_t u;
    asm("cvt.rna.tf32.f32 %0, %1;" : "=r"(u) : "f"(f));
    return u;
}

__device__ __forceinline__ void mma8(float* c, const uint32_t* a, const uint32_t* b) {
    asm volatile(
        "mma.sync.aligned.m16n8k8.row.col.f32.tf32.tf32.f32 "
        "{%0,%1,%2,%3},{%4,%5,%6,%7},{%8,%9},{%0,%1,%2,%3};"
        : "+f"(c[0]), "+f"(c[1]), "+f"(c[2]), "+f"(c[3])
        : "r"(a[0]), "r"(a[1]), "r"(a[2]), "r"(a[3]), "r"(b[0]), "r"(b[1]));
}

__device__ __forceinline__ void cp16(uint32_t dst, const void* src) {
    asm volatile("cp.async.cg.shared.global [%0], [%1], 16;"
                 :: "r"(dst), "l"(src));
}
__device__ __forceinline__ void cp_commit() {
    asm volatile("cp.async.commit_group;");
}
__device__ __forceinline__ void cp_wait1() {
    asm volatile("cp.async.wait_group 1;");
}
__device__ __forceinline__ void cp_wait0() {
    asm volatile("cp.async.wait_group 0;");
}

__device__ __forceinline__ int rp_bucket(int rp) {
    if (rp < 0) rp = 0;
    if (rp < 16) return rp;
    int bk = 16 + (int)(__logf((float)rp * 0.0625f) * 7.6944086f);
    return bk > 31 ? 31 : bk;
}

// ---------------------------------------------------------------------------
// Kernel 1: fused RMS norm: xn = x * rsqrt(mean(x^2)+eps) * lnw
// ---------------------------------------------------------------------------
__global__ __launch_bounds__(256) void norm_kernel(
    const float* __restrict__ x, const float* __restrict__ lnw,
    float* __restrict__ xn)
{
    int row = blockIdx.x;
    const float4* xr = (const float4*)(x + (size_t)row * Dq);
    float4 v = xr[threadIdx.x];
    float s = v.x * v.x + v.y * v.y + v.z * v.z + v.w * v.w;
    __shared__ float red[8];
    #pragma unroll
    for (int o = 16; o > 0; o >>= 1) s += __shfl_xor_sync(0xffffffffu, s, o);
    if ((threadIdx.x & 31) == 0) red[threadIdx.x >> 5] = s;
    __syncthreads();
    float t = 0.f;
    #pragma unroll
    for (int i = 0; i < 8; i++) t += red[i];
    float rs = rsqrtf(t * (1.0f / (float)Dq) + 1e-6f);
    float4 lw = ((const float4*)lnw)[threadIdx.x];
    float4 o4 = { v.x * rs * lw.x, v.y * rs * lw.y,
                  v.z * rs * lw.z, v.w * rs * lw.w };
    ((float4*)(xn + (size_t)row * Dq))[threadIdx.x] = o4;
}

// ---------------------------------------------------------------------------
// Kernel 2: tf32 tensor-core GEMM, 3-stage cp.async pipeline.
// BM=BN=128, BK=32, 256 threads, 2 CTAs/SM, warp grid 2(M)x4(N), 4x4 m16n8.
// smem: 3 x (128x36 + 32x136) words = 107520 B.
// ---------------------------------------------------------------------------
#define GA_ST    36
#define GB_ST    136
#define GA_WORDS (128 * GA_ST)           // 4608 per stage
#define GB_WORDS (32 * GB_ST)            // 4352 per stage
#define GB_BASE  (3 * GA_WORDS)          // 13824
#define GEMM_SMEM_BYTES ((3 * GA_WORDS + 3 * GB_WORDS) * 4)  // 107520
#define NKT (Dq / 32)                    // 32 k-tiles

template<bool RES>
__global__ __launch_bounds__(256, 2) void gemm_tc2(
    const float* __restrict__ A, const float* __restrict__ W,
    float* __restrict__ C, const float* __restrict__ res)
{
    extern __shared__ float smf[];
    uint32_t smb = (uint32_t)__cvta_generic_to_shared(smf);

    const int col0 = blockIdx.x << 7;
    const int row0 = blockIdx.y << 7;

    const int tid = threadIdx.x;
    const int wid = tid >> 5, lane = tid & 31;
    const int lq = lane >> 2, lr = lane & 3;
    const int warpM = (wid & 1) * 64;
    const int warpN = (wid >> 1) * 32;

    const int ar = tid >> 3, ac = (tid & 7) << 2;
    const int br = tid >> 5, bc = (tid & 31) << 2;

    auto copyTile = [&](int t, int st) {
        int k0 = t * 32;
        #pragma unroll
        for (int u = 0; u < 4; u++) {
            int r = ar + u * 32;
            uint32_t dst = smb + (st * GA_WORDS + r * GA_ST + ac) * 4;
            cp16(dst, A + (size_t)(row0 + r) * Dq + k0 + ac);
        }
        #pragma unroll
        for (int u = 0; u < 4; u++) {
            int r = br + u * 8;
            uint32_t dst = smb + (GB_BASE + st * GB_WORDS + r * GB_ST + bc) * 4;
            cp16(dst, W + (size_t)(k0 + r) * Dq + col0 + bc);
        }
        cp_commit();
    };

    float acc[4][4][4] = {};

    copyTile(0, 0);
    copyTile(1, 1);

    #pragma unroll 1
    for (int t = 0; t < NKT; t++) {
        int stage = t % 3;
        if (t + 1 < NKT) cp_wait1(); else cp_wait0();
        __syncthreads();
        if (t + 2 < NKT) copyTile(t + 2, (t + 2) % 3);

        const float* As = smf + stage * GA_WORDS;
        const float* Bs = smf + GB_BASE + stage * GB_WORDS;

        #pragma unroll
        for (int ks = 0; ks < 4; ks++) {
            uint32_t a[4][4], b[4][2];
            #pragma unroll
            for (int mt = 0; mt < 4; mt++) {
                int rb = warpM + mt * 16 + lq;
                int cb = ks * 8 + lr;
                a[mt][0] = f2tf(As[rb * GA_ST + cb]);
                a[mt][1] = f2tf(As[(rb + 8) * GA_ST + cb]);
                a[mt][2] = f2tf(As[rb * GA_ST + cb + 4]);
                a[mt][3] = f2tf(As[(rb + 8) * GA_ST + cb + 4]);
            }
            #pragma unroll
            for (int nt = 0; nt < 4; nt++) {
                int nb = warpN + nt * 8 + lq;
                b[nt][0] = f2tf(Bs[(ks * 8 + lr) * GB_ST + nb]);
                b[nt][1] = f2tf(Bs[(ks * 8 + lr + 4) * GB_ST + nb]);
            }
            #pragma unroll
            for (int mt = 0; mt < 4; mt++)
                #pragma unroll
                for (int nt = 0; nt < 4; nt++)
                    mma8(acc[mt][nt], a[mt], b[nt]);
        }
    }

    #pragma unroll
    for (int mt = 0; mt < 4; mt++)
        #pragma unroll
        for (int nt = 0; nt < 4; nt++) {
            int row = row0 + warpM + mt * 16 + lq;
            int col = col0 + warpN + nt * 8 + lr * 2;
            float2 v0 = { acc[mt][nt][0], acc[mt][nt][1] };
            float2 v1 = { acc[mt][nt][2], acc[mt][nt][3] };
            if (RES) {
                float2 r0 = *(const float2*)&res[(size_t)row * Dq + col];
                float2 r1 = *(const float2*)&res[(size_t)(row + 8) * Dq + col];
                v0.x += r0.x; v0.y += r0.y; v1.x += r1.x; v1.y += r1.y;
            }
            *(float2*)&C[(size_t)row * Dq + col] = v0;
            *(float2*)&C[(size_t)(row + 8) * Dq + col] = v1;
        }
}

// ---------------------------------------------------------------------------
// Kernel 3: flash attention, tf32 tensor cores. Forced 2 CTAs/SM.
// ---------------------------------------------------------------------------
#define QS(r, c) sm[(r) * 68 + (c)]
#define KS(r, c) sm[8704 + (r) * 68 + (c)]
#define VS(r, c) sm[13056 + (r) * 72 + (c)]
#define PS(r, c) sm[17664 + (r) * 68 + (c)]
#define FLASH_SMEM_WORDS (17664 + 128 * 68)

__global__ __launch_bounds__(256, 2) void flash_tc(const float* __restrict__ rel_emb)
{
    extern __shared__ uint32_t sm[];
    __shared__ float bias_tab[32];

    const int tid = threadIdx.x;
    const int wid = tid >> 5, lane = tid & 31;
    const int lq = lane >> 2, lr = lane & 3;
    const int warpRow = wid * 16;

    const int q0 = blockIdx.x << 7;
    const int bh = blockIdx.y;
    const int b = bh >> 4, h = bh & 15;
    const size_t base = ((size_t)b * Sq) * Dq + (size_t)h * HDq;

    if (tid < 32) bias_tab[tid] = rel_emb[tid * Hq + h];

    #pragma unroll
    for (int u = 0; u < 8; u++) {
        int lin = tid + u * 256;
        int r = lin >> 4, c4 = (lin & 15) << 2;
        float4 qv = *(const float4*)&g_q[base + (size_t)(q0 + r) * Dq + c4];
        uint4 qt = { f2tf(qv.x), f2tf(qv.y), f2tf(qv.z), f2tf(qv.w) };
        *(uint4*)&QS(r, c4) = qt;
    }

    const float NEG_INF = __int_as_float(0xff800000u);
    float mA = NEG_INF, mB = NEG_INF, lA = 0.f, lB = 0.f;
    float o[8][4] = {};
    const int rowA = q0 + warpRow + lq;

    for (int k0 = 0; k0 < Sq; k0 += 64) {
        __syncthreads();
        #pragma unroll
        for (int u = 0; u < 4; u++) {
            int lin = tid + u * 256;
            int r = lin >> 4, c4 = (lin & 15) << 2;
            float4 kv = *(const float4*)&g_k[base + (size_t)(k0 + r) * Dq + c4];
            uint4 kt = { f2tf(kv.x), f2tf(kv.y), f2tf(kv.z), f2tf(kv.w) };
            *(uint4*)&KS(r, c4) = kt;
            float4 vv = *(const float4*)&g_v[base + (size_t)(k0 + r) * Dq + c4];
            uint4 vt = { f2tf(vv.x), f2tf(vv.y), f2tf(vv.z), f2tf(vv.w) };
            *(uint4*)&VS(r, c4) = vt;
        }
        __syncthreads();

        float s[8][4] = {};
        uint32_t aq[8][4];
        #pragma unroll
        for (int ks = 0; ks < 8; ks++) {
            int rb = warpRow + lq, cb = ks * 8 + lr;
            aq[ks][0] = QS(rb, cb);     aq[ks][1] = QS(rb + 8, cb);
            aq[ks][2] = QS(rb, cb + 4); aq[ks][3] = QS(rb + 8, cb + 4);
        }
        #pragma unroll
        for (int nt = 0; nt < 8; nt++) {
            #pragma unroll
            for (int ks = 0; ks < 8; ks++) {
                uint32_t bb[2];
                bb[0] = KS(nt * 8 + lq, ks * 8 + lr);
                bb[1] = KS(nt * 8 + lq, ks * 8 + lr + 4);
                mma8(s[nt], aq[ks], bb);
            }
        }

        #pragma unroll
        for (int nt = 0; nt < 8; nt++) {
            int kc = k0 + nt * 8 + lr * 2;
            s[nt][0] += bias_tab[rp_bucket(rowA - kc)];
            s[nt][1] += bias_tab[rp_bucket(rowA - kc - 1)];
            s[nt][2] += bias_tab[rp_bucket(rowA + 8 - kc)];
            s[nt][3] += bias_tab[rp_bucket(rowA + 8 - kc - 1)];
        }

        float mxA = NEG_INF, mxB = NEG_INF;
        #pragma unroll
        for (int nt = 0; nt < 8; nt++) {
            mxA = fmaxf(mxA, fmaxf(s[nt][0], s[nt][1]));
            mxB = fmaxf(mxB, fmaxf(s[nt][2], s[nt][3]));
        }
        mxA = fmaxf(mxA, __shfl_xor_sync(0xffffffffu, mxA, 1));
        mxA = fmaxf(mxA, __shfl_xor_sync(0xffffffffu, mxA, 2));
        mxB = fmaxf(mxB, __shfl_xor_sync(0xffffffffu, mxB, 1));
        mxB = fmaxf(mxB, __shfl_xor_sync(0xffffffffu, mxB, 2));
        float nmA = fmaxf(mA, mxA), nmB = fmaxf(mB, mxB);
        float alA = __expf(mA - nmA), alB = __expf(mB - nmB);
        float sumA = 0.f, sumB = 0.f;
        #pragma unroll
        for (int nt = 0; nt < 8; nt++) {
            s[nt][0] = __expf(s[nt][0] - nmA); sumA += s[nt][0];
            s[nt][1] = __expf(s[nt][1] - nmA); sumA += s[nt][1];
            s[nt][2] = __expf(s[nt][2] - nmB); sumB += s[nt][2];
            s[nt][3] = __expf(s[nt][3] - nmB); sumB += s[nt][3];
        }
        sumA += __shfl_xor_sync(0xffffffffu, sumA, 1);
        sumA += __shfl_xor_sync(0xffffffffu, sumA, 2);
        sumB += __shfl_xor_sync(0xffffffffu, sumB, 1);
        sumB += __shfl_xor_sync(0xffffffffu, sumB, 2);
        lA = lA * alA + sumA; mA = nmA;
        lB = lB * alB + sumB; mB = nmB;
        #pragma unroll
        for (int nt = 0; nt < 8; nt++) {
            o[nt][0] *= alA; o[nt][1] *= alA;
            o[nt][2] *= alB; o[nt][3] *= alB;
        }

        #pragma unroll
        for (int nt = 0; nt < 8; nt++) {
            int c = nt * 8 + lr * 2;
            PS(warpRow + lq, c)     = f2tf(s[nt][0]);
            PS(warpRow + lq, c + 1) = f2tf(s[nt][1]);
            PS(warpRow + 8 + lq, c)     = f2tf(s[nt][2]);
            PS(warpRow + 8 + lq, c + 1) = f2tf(s[nt][3]);
        }
        __syncwarp();

        #pragma unroll
        for (int ks = 0; ks < 8; ks++) {
            uint32_t ap[4];
            int cb = ks * 8 + lr;
            ap[0] = PS(warpRow + lq, cb);     ap[1] = PS(warpRow + 8 + lq, cb);
            ap[2] = PS(warpRow + lq, cb + 4); ap[3] = PS(warpRow + 8 + lq, cb + 4);
            #pragma unroll
            for (int nt = 0; nt < 8; nt++) {
                uint32_t bb[2];
                bb[0] = VS(ks * 8 + lr, nt * 8 + lq);
                bb[1] = VS(ks * 8 + lr + 4, nt * 8 + lq);
                mma8(o[nt], ap, bb);
            }
        }
    }

    float invA = 1.0f / lA, invB = 1.0f / lB;
    #pragma unroll
    for (int nt = 0; nt < 8; nt++) {
        int col = nt * 8 + lr * 2;
        float2 vA = { o[nt][0] * invA, o[nt][1] * invA };
        float2 vB = { o[nt][2] * invB, o[nt][3] * invB };
        *(float2*)&g_ctx[base + (size_t)rowA * Dq + col] = vA;
        *(float2*)&g_ctx[base + (size_t)(rowA + 8) * Dq + col] = vB;
    }
}

// ---------------------------------------------------------------------------
// Launch
// ---------------------------------------------------------------------------
extern "C" void kernel_launch(void* const* d_in, const int* in_sizes, int n_in,
                              void* d_out, int out_size)
{
    const float* input = (const float*)d_in[0];
    const float* wq    = (const float*)d_in[2];
    const float* wk    = (const float*)d_in[3];
    const float* wv    = (const float*)d_in[4];
    const float* wo    = (const float*)d_in[5];
    const float* rel   = (const float*)d_in[6];
    const float* lnw   = (const float*)d_in[7];
    float* out         = (float*)d_out;

    static const int FLASH_SMEM = FLASH_SMEM_WORDS * 4;
    cudaFuncSetAttribute(flash_tc,
                         cudaFuncAttributeMaxDynamicSharedMemorySize, FLASH_SMEM);
    cudaFuncSetAttribute(gemm_tc2<false>,
                         cudaFuncAttributeMaxDynamicSharedMemorySize, GEMM_SMEM_BYTES);
    cudaFuncSetAttribute(gemm_tc2<true>,
                         cudaFuncAttributeMaxDynamicSharedMemorySize, GEMM_SMEM_BYTES);

    float *g_xn_p, *g_q_p, *g_k_p, *g_v_p, *g_ctx_p;
    cudaGetSymbolAddress((void**)&g_xn_p, g_xn);
    cudaGetSymbolAddress((void**)&g_q_p,  g_q);
    cudaGetSymbolAddress((void**)&g_k_p,  g_k);
    cudaGetSymbolAddress((void**)&g_v_p,  g_v);
    cudaGetSymbolAddress((void**)&g_ctx_p, g_ctx);

    norm_kernel<<<Mq, 256>>>(input, lnw, g_xn_p);

    dim3 gg(Dq / 128, Mq / 128);
    gemm_tc2<false><<<gg, 256, GEMM_SMEM_BYTES>>>(g_xn_p, wq, g_q_p, nullptr);
    gemm_tc2<false><<<gg, 256, GEMM_SMEM_BYTES>>>(g_xn_p, wk, g_k_p, nullptr);
    gemm_tc2<false><<<gg, 256, GEMM_SMEM_BYTES>>>(g_xn_p, wv, g_v_p, nullptr);

    dim3 gf(Sq / 128, Bq * Hq);
    flash_tc<<<gf, 256, FLASH_SMEM>>>(rel);

    gemm_tc2<true><<<gg, 256, GEMM_SMEM_BYTES>>>(g_ctx_p, wo, out, input);
}